// round 15
// baseline (speedup 1.0000x reference)
#include <cuda_runtime.h>
#include <cuda_fp16.h>
#include <cuda_bf16.h>
#include <cstdint>

// ---------------------------------------------------------------------------
// Problem constants
// ---------------------------------------------------------------------------
#define B_WIN   2048
#define NTOK    49
#define DMODEL  768
#define NHEADS  24
#define HDIM    32
#define NW      64
#define MROWS   (B_WIN * NTOK)     // 100352
#define QKV_N   (3 * DMODEL)       // 2304
#define KDIM    768
#define KPITCH  (KDIM * 2)         // bytes per K-major row (fp16)

// ---------------------------------------------------------------------------
// scratch (__device__ globals, allocation-free)
// ---------------------------------------------------------------------------
__device__ __half g_qkv16[(size_t)MROWS * QKV_N];
__device__ __half g_x16 [(size_t)MROWS * KDIM];
__device__ __half g_a16 [(size_t)MROWS * KDIM];
__device__ __half g_w1hi[(size_t)QKV_N * KDIM];
__device__ __half g_w2hi[(size_t)DMODEL * KDIM];

// ---------------------------------------------------------------------------
// PTX helpers
// ---------------------------------------------------------------------------
__device__ __forceinline__ void cp16(uint32_t dst, const void* src) {
    asm volatile("cp.async.cg.shared.global [%0], [%1], 16;"
                 :: "r"(dst), "l"((unsigned long long)__cvta_generic_to_global(src))
                 : "memory");
}
__device__ __forceinline__ void ldsm4(uint32_t* r, uint32_t addr) {
    asm volatile("ldmatrix.sync.aligned.m8n8.x4.shared.b16 {%0,%1,%2,%3}, [%4];"
                 : "=r"(r[0]), "=r"(r[1]), "=r"(r[2]), "=r"(r[3]) : "r"(addr));
}
__device__ __forceinline__ void mma_fp16(float* c, const uint32_t* a,
                                         uint32_t b0, uint32_t b1) {
    asm volatile(
        "mma.sync.aligned.m16n8k16.row.col.f32.f16.f16.f32 "
        "{%0,%1,%2,%3}, {%4,%5,%6,%7}, {%8,%9}, {%0,%1,%2,%3};"
        : "+f"(c[0]), "+f"(c[1]), "+f"(c[2]), "+f"(c[3])
        : "r"(a[0]), "r"(a[1]), "r"(a[2]), "r"(a[3]), "r"(b0), "r"(b1));
}
// packed fp32x2 (Blackwell FFMA2 — PTX-only)
__device__ __forceinline__ unsigned long long dup_f32(float x) {
    unsigned long long r;
    asm("mov.b64 %0, {%1, %1};" : "=l"(r) : "f"(x));
    return r;
}
__device__ __forceinline__ unsigned long long pack_f32(float lo, float hi) {
    unsigned long long r;
    asm("mov.b64 %0, {%1, %2};" : "=l"(r) : "f"(lo), "f"(hi));
    return r;
}
__device__ __forceinline__ void fma2(unsigned long long& d,
                                     unsigned long long a,
                                     unsigned long long b) {
    asm("fma.rn.f32x2 %0, %1, %2, %0;" : "+l"(d) : "l"(a), "l"(b));
}
__device__ __forceinline__ void unpack2(unsigned long long v, float& lo, float& hi) {
    asm("mov.b64 {%0, %1}, %2;" : "=f"(lo), "=f"(hi) : "l"(v));
}
__device__ __forceinline__ void h8_to_f8(uint4 u, float* f) {
    const __half2* hp = (const __half2*)&u;
    float2 f0 = __half22float2(hp[0]);
    float2 f1 = __half22float2(hp[1]);
    float2 f2 = __half22float2(hp[2]);
    float2 f3 = __half22float2(hp[3]);
    f[0] = f0.x; f[1] = f0.y; f[2] = f1.x; f[3] = f1.y;
    f[4] = f2.x; f[5] = f2.y; f[6] = f3.x; f[7] = f3.y;
}

extern __shared__ char dyn_smem[];

// ---------------------------------------------------------------------------
// GEMM (single-term fp16): C = A_fp16 @ B^T + bias.
// 128 threads / 4 warps, warp tile 64x64 (MMA:ldsm = 4:1), BM=BN=128, BK=64,
// 3-stage cp.async, 2 CTAs/SM (regs capped at 256 by launch bounds).
// ---------------------------------------------------------------------------
#define BM 128
#define BN 128
#define BK 64
#define NCHUNK (KDIM / BK)    // 12
#define NSTAGE 3
#define A_OFF  0u
#define B_OFF  16384u
#define STG_B  32768u
#define GEMM_SMEM (NSTAGE * STG_B)   // 98304

// 128B rows, slot c16 in [0,8): swizzled by row&7
__device__ __forceinline__ uint32_t swz128(int row, int c16) {
    return (uint32_t)(row * 128 + (((c16) ^ (row & 7)) << 4));
}

__global__ void __launch_bounds__(128, 2)
gemm_mma_kernel(const __half* __restrict__ A,
                const __half* __restrict__ B,
                const float* __restrict__ bias,
                float* __restrict__ C32,
                __half* __restrict__ C16, int N)
{
    const uint32_t sb = (uint32_t)__cvta_generic_to_shared(dyn_smem);
    const int tid    = threadIdx.x;
    const int wid    = tid >> 5;
    const int lane   = tid & 31;
    const int warp_m = wid & 1;     // 64 rows
    const int warp_n = wid >> 1;    // 64 cols
    const int brow   = blockIdx.y * BM;
    const int bcol   = blockIdx.x * BN;

    const char* pA = (const char*)A + (size_t)brow * KPITCH;
    const char* pB = (const char*)B + (size_t)bcol * KPITCH;

    float acc[4][8][4];
#pragma unroll
    for (int mt = 0; mt < 4; mt++)
#pragma unroll
        for (int nt = 0; nt < 8; nt++)
#pragma unroll
            for (int q = 0; q < 4; q++) acc[mt][nt][q] = 0.f;

    auto load_stage = [&](int c, int s) {
        const uint32_t st = sb + s * STG_B;
        const int koff = c * 128;    // 64 halfs = 128 bytes
#pragma unroll
        for (int r = 0; r < 8; r++) {
            int p    = tid + r * 128;      // 0..1023
            int row  = p >> 3;             // 0..127
            int c16  = p & 7;
            uint32_t so = swz128(row, c16);
            size_t   go = (size_t)row * KPITCH + koff + c16 * 16;
            cp16(st + A_OFF + so, pA + go);
            cp16(st + B_OFF + so, pB + go);
        }
        asm volatile("cp.async.commit_group;" ::: "memory");
    };

    load_stage(0, 0);
    load_stage(1, 1);

    for (int c = 0; c < NCHUNK; c++) {
        if (c < NCHUNK - 1)
            asm volatile("cp.async.wait_group 1;" ::: "memory");
        else
            asm volatile("cp.async.wait_group 0;" ::: "memory");
        __syncthreads();

        if (c + 2 < NCHUNK) load_stage(c + 2, (c + 2) % 3);

        const uint32_t st = sb + (c % 3) * STG_B;
#pragma unroll
        for (int ks = 0; ks < 4; ks++) {           // 4 k-steps of 16
            uint32_t a[4][4];
#pragma unroll
            for (int mt = 0; mt < 4; mt++) {
                int row = warp_m * 64 + mt * 16 + (lane & 7) + ((lane >> 3) & 1) * 8;
                int c16 = 2 * ks + ((lane >> 4) & 1);
                ldsm4(a[mt], st + A_OFF + swz128(row, c16));
            }
            uint32_t bh[4][4];
#pragma unroll
            for (int np = 0; np < 4; np++) {
                int rowb = warp_n * 64 + np * 16 + (lane & 7) + ((lane >> 4) & 1) * 8;
                int c16  = 2 * ks + ((lane >> 3) & 1);
                ldsm4(bh[np], st + B_OFF + swz128(rowb, c16));
            }
#pragma unroll
            for (int np = 0; np < 4; np++)
#pragma unroll
                for (int t = 0; t < 2; t++)
#pragma unroll
                    for (int mt = 0; mt < 4; mt++)
                        mma_fp16(acc[mt][np*2+t], a[mt], bh[np][t*2], bh[np][t*2+1]);
        }
    }

    const int row0 = brow + warp_m * 64;
    const int col0 = bcol + warp_n * 64;
#pragma unroll
    for (int mt = 0; mt < 4; mt++) {
#pragma unroll
        for (int nt = 0; nt < 8; nt++) {
            int r  = row0 + mt * 16 + (lane >> 2);
            int cc = col0 + nt * 8 + (lane & 3) * 2;
            float2 bv = *(const float2*)(bias + cc);
            float o0x = acc[mt][nt][0] + bv.x, o0y = acc[mt][nt][1] + bv.y;
            float o1x = acc[mt][nt][2] + bv.x, o1y = acc[mt][nt][3] + bv.y;
            if (C16) {
                __half2 h0 = __floats2half2_rn(o0x, o0y);
                __half2 h1 = __floats2half2_rn(o1x, o1y);
                *(uint32_t*)(C16 + (size_t)r * N + cc)       = *(uint32_t*)&h0;
                *(uint32_t*)(C16 + (size_t)(r + 8) * N + cc) = *(uint32_t*)&h1;
            } else {
                *(float2*)(C32 + (size_t)r * N + cc)       = make_float2(o0x, o0y);
                *(float2*)(C32 + (size_t)(r + 8) * N + cc) = make_float2(o1x, o1y);
            }
        }
    }
}

// ---------------------------------------------------------------------------
// convert f32 -> fp16
// ---------------------------------------------------------------------------
__global__ void __launch_bounds__(256)
conv16_kernel(const float4* __restrict__ in, uint2* __restrict__ out, int n4)
{
    int i = blockIdx.x * 256 + threadIdx.x;
    if (i >= n4) return;
    float4 v = in[i];
    __half2 h0 = __floats2half2_rn(v.x, v.y);
    __half2 h1 = __floats2half2_rn(v.z, v.w);
    uint2 o;
    o.x = *(uint32_t*)&h0;
    o.y = *(uint32_t*)&h1;
    out[i] = o;
}

// ---------------------------------------------------------------------------
// weight transpose to fp16: W[K,N] f32 -> [N,K] fp16
// ---------------------------------------------------------------------------
__global__ void __launch_bounds__(256)
wtrans_kernel(const float* __restrict__ W, __half* __restrict__ hi, int K, int N)
{
    __shared__ float t[32][33];
    const int n0 = blockIdx.x * 32, k0 = blockIdx.y * 32;
    const int tx = threadIdx.x & 31, ty = threadIdx.x >> 5;
#pragma unroll
    for (int r = 0; r < 32; r += 8)
        t[ty + r][tx] = W[(size_t)(k0 + ty + r) * N + n0 + tx];
    __syncthreads();
#pragma unroll
    for (int r = 0; r < 32; r += 8) {
        float v = t[tx][ty + r];
        hi[(size_t)(n0 + ty + r) * K + k0 + tx] = __float2half_rn(v);
    }
}

// ---------------------------------------------------------------------------
// Attention: row-batched f32x2 design; q pre-duplicated in smem as packed
// u64 pairs (kills the per-iteration mov.b64 dups in the qk loop).
// ---------------------------------------------------------------------------
#define VT_STRIDE 52
#define RPW 13

__global__ void __launch_bounds__(128)
attn_kernel(const __half* __restrict__ qkv16,
            const float* __restrict__ mask,
            const float* __restrict__ bias_table,
            __half* __restrict__ out16)
{
    const int bh = blockIdx.x;
    const int b  = bh / NHEADS;
    const int h  = bh - b * NHEADS;
    const int w  = b & (NW - 1);

    __shared__ unsigned long long qd[NTOK * HDIM];   // {q,q} pairs, 12544 B
    __shared__ unsigned long long kp2[HDIM * 32];    // {k[j],k[j+32]}, 8192 B
    __shared__ float vt[HDIM * VT_STRIDE];           // 6656 B
    __shared__ float pbuf[4][RPW][64];               // 13312 B
    __shared__ float bt[169];

    const int tid  = threadIdx.x;
    const int warp = tid >> 5, lane = tid & 31;
    const __half* base = qkv16 + (size_t)b * NTOK * QKV_N + h * HDIM;

    // ---- q fill: convert + duplicate into u64 pairs ----
    for (int idx = tid; idx < NTOK * 4; idx += 128) {
        int i = idx >> 2, m = idx & 3;
        uint4 u = *(const uint4*)(base + (size_t)i * QKV_N + m * 8);
        float f[8];
        h8_to_f8(u, f);
#pragma unroll
        for (int p = 0; p < 8; p++)
            qd[i * HDIM + m * 8 + p] = dup_f32(f[p]);
    }
    // ---- K fill: warp covers dims d0 = 8w..8w+7, lane = j ----
    {
        const int d0 = warp * 8;
        const int j  = lane;
        float k1v[8], k2v[8];
        uint4 u1 = *(const uint4*)(base + (size_t)j * QKV_N + DMODEL + d0);
        h8_to_f8(u1, k1v);
        if (j < NTOK - 32) {
            uint4 u2 = *(const uint4*)(base + (size_t)(j + 32) * QKV_N + DMODEL + d0);
            h8_to_f8(u2, k2v);
        } else {
#pragma unroll
            for (int p = 0; p < 8; p++) k2v[p] = 0.f;
        }
#pragma unroll
        for (int p = 0; p < 8; p++)
            kp2[(d0 + p) * 32 + j] = pack_f32(k1v[p], k2v[p]);
    }
    // ---- V^T fill ----
    if (tid < NTOK) {
        const __half* vrow = base + (size_t)tid * QKV_N + 2 * DMODEL;
#pragma unroll
        for (int m = 0; m < 4; m++) {
            float f[8];
            h8_to_f8(((const uint4*)vrow)[m], f);
#pragma unroll
            for (int p = 0; p < 8; p++)
                vt[(8 * m + p) * VT_STRIDE + tid] = f[p];
        }
    }
    if (tid >= 64 && tid < 96) {
        int d = tid - 64;
        vt[d * VT_STRIDE + 49] = 0.f;
        vt[d * VT_STRIDE + 50] = 0.f;
        vt[d * VT_STRIDE + 51] = 0.f;
    }
    for (int idx = tid; idx < 169; idx += 128)
        bt[idx] = bias_table[idx * NHEADS + h];
    __syncthreads();

    const float scale = 0.17677669529663687f;
    const float* mrow_base = mask + (size_t)w * NTOK * NTOK;

    const int row0 = warp * RPW;
    const int nr   = (NTOK - row0 < RPW) ? (NTOK - row0) : RPW;

    const int yq  = lane / 7, xq  = lane - yq * 7;
    const int j2l = lane + 32;
    const int yq2 = j2l / 7,  xq2 = j2l - yq2 * 7;

    // ---- qk: rows batched; q read as pre-duplicated u64 pairs ----
    unsigned long long d12[RPW];
#pragma unroll
    for (int r = 0; r < RPW; r++) d12[r] = 0ull;

#pragma unroll
    for (int m = 0; m < 8; m++) {
        unsigned long long k0 = kp2[(4 * m + 0) * 32 + lane];
        unsigned long long k1 = kp2[(4 * m + 1) * 32 + lane];
        unsigned long long k2 = kp2[(4 * m + 2) * 32 + lane];
        unsigned long long k3 = kp2[(4 * m + 3) * 32 + lane];
#pragma unroll
        for (int r = 0; r < RPW; r++) {
            int i = row0 + ((r < nr) ? r : 0);
            ulonglong2 qa = *(const ulonglong2*)&qd[i * HDIM + 4 * m];
            ulonglong2 qb = *(const ulonglong2*)&qd[i * HDIM + 4 * m + 2];
            fma2(d12[r], k0, qa.x);
            fma2(d12[r], k1, qa.y);
            fma2(d12[r], k2, qb.x);
            fma2(d12[r], k3, qb.y);
        }
    }

    // ---- softmax per row ----
#pragma unroll
    for (int r = 0; r < RPW; r++) {
        int i = row0 + ((r < nr) ? r : 0);
        const int yi = i / 7, xi = i - yi * 7;
        const float* mrow = mrow_base + (size_t)i * NTOK;

        float d1, d2;
        unpack2(d12[r], d1, d2);
        float l1 = d1 * scale + bt[(yi - yq + 6) * 13 + (xi - xq + 6)] + mrow[lane];
        float p1 = __expf(l1);
        float p2 = 0.f;
        if (lane < NTOK - 32) {
            float l2 = d2 * scale + bt[(yi - yq2 + 6) * 13 + (xi - xq2 + 6)]
                     + mrow[j2l];
            p2 = __expf(l2);
        }
        float s = p1 + p2;
#pragma unroll
        for (int o = 16; o > 0; o >>= 1)
            s += __shfl_xor_sync(0xffffffffu, s, o);
        float inv = 1.f / s;
        pbuf[warp][r][lane]      = p1 * inv;
        pbuf[warp][r][lane + 32] = p2 * inv;
    }
    __syncwarp();

    // ---- p.v: rows batched ----
    unsigned long long a2[RPW];
#pragma unroll
    for (int r = 0; r < RPW; r++) a2[r] = 0ull;

#pragma unroll
    for (int j4 = 0; j4 < 13; j4++) {
        ulonglong2 vq = *(const ulonglong2*)&vt[lane * VT_STRIDE + j4 * 4];
#pragma unroll
        for (int r = 0; r < RPW; r++) {
            ulonglong2 pq = *(const ulonglong2*)&pbuf[warp][r][j4 * 4];
            fma2(a2[r], pq.x, vq.x);
            fma2(a2[r], pq.y, vq.y);
        }
    }

#pragma unroll
    for (int r = 0; r < RPW; r++) {
        if (r < nr) {
            float alo_, ahi_;
            unpack2(a2[r], alo_, ahi_);
            float acc = alo_ + ahi_;
            int i = row0 + r;
            size_t oidx = ((size_t)b * NTOK + i) * DMODEL + h * HDIM + lane;
            out16[oidx] = __float2half_rn(acc);
        }
    }
}

// ---------------------------------------------------------------------------
// launch
// ---------------------------------------------------------------------------
extern "C" void kernel_launch(void* const* d_in, const int* in_sizes, int n_in,
                              void* d_out, int out_size)
{
    const float* x          = (const float*)d_in[0];
    const float* mask       = (const float*)d_in[1];
    const float* qkv_w      = (const float*)d_in[2];
    const float* qkv_b      = (const float*)d_in[3];
    const float* proj_w     = (const float*)d_in[4];
    const float* proj_b     = (const float*)d_in[5];
    const float* bias_table = (const float*)d_in[6];
    float* out = (float*)d_out;

    __half *qkv16, *x16, *a16, *w1hi, *w2hi;
    cudaGetSymbolAddress((void**)&qkv16, g_qkv16);
    cudaGetSymbolAddress((void**)&x16,  g_x16);
    cudaGetSymbolAddress((void**)&a16,  g_a16);
    cudaGetSymbolAddress((void**)&w1hi, g_w1hi);
    cudaGetSymbolAddress((void**)&w2hi, g_w2hi);

    cudaFuncSetAttribute(gemm_mma_kernel,
                         cudaFuncAttributeMaxDynamicSharedMemorySize, GEMM_SMEM);

    // 0) conversions
    {
        int n4 = (MROWS * KDIM) / 4;
        conv16_kernel<<<(n4 + 255) / 256, 256>>>((const float4*)x, (uint2*)x16, n4);
        dim3 g1(QKV_N / 32, KDIM / 32);
        wtrans_kernel<<<g1, 256>>>(qkv_w, w1hi, KDIM, QKV_N);
        dim3 g2(DMODEL / 32, KDIM / 32);
        wtrans_kernel<<<g2, 256>>>(proj_w, w2hi, KDIM, DMODEL);
    }
    // 1) QKV GEMM (single-term fp16, BK=64, 64x64 warp tiles) -> fp16
    {
        dim3 grid(QKV_N / BN, MROWS / BM);
        gemm_mma_kernel<<<grid, 128, GEMM_SMEM>>>(x16, w1hi,
                                                  qkv_b, nullptr, qkv16, QKV_N);
    }
    // 2) attention (row-batched, q-dedup, fp16 in/out)
    attn_kernel<<<B_WIN * NHEADS, 128>>>(qkv16, mask, bias_table, a16);

    // 3) proj GEMM (single-term fp16) -> fp32 d_out
    {
        dim3 grid(DMODEL / BN, MROWS / BM);
        gemm_mma_kernel<<<grid, 128, GEMM_SMEM>>>(a16, w2hi,
                                                  proj_b, out, nullptr, DMODEL);
    }
}

// round 16
// speedup vs baseline: 1.0810x; 1.0810x over previous
#include <cuda_runtime.h>
#include <cuda_fp16.h>
#include <cuda_bf16.h>
#include <cstdint>

// ---------------------------------------------------------------------------
// Problem constants
// ---------------------------------------------------------------------------
#define B_WIN   2048
#define NTOK    49
#define DMODEL  768
#define NHEADS  24
#define HDIM    32
#define NW      64
#define MROWS   (B_WIN * NTOK)     // 100352
#define QKV_N   (3 * DMODEL)       // 2304
#define KDIM    768
#define KPITCH  (KDIM * 2)         // bytes per K-major row (fp16)

// ---------------------------------------------------------------------------
// scratch (__device__ globals, allocation-free)
// ---------------------------------------------------------------------------
__device__ __half g_qkv16[(size_t)MROWS * QKV_N];
__device__ __half g_x16 [(size_t)MROWS * KDIM];
__device__ __half g_a16 [(size_t)MROWS * KDIM];
__device__ __half g_w1hi[(size_t)QKV_N * KDIM];
__device__ __half g_w2hi[(size_t)DMODEL * KDIM];

// ---------------------------------------------------------------------------
// PTX helpers
// ---------------------------------------------------------------------------
__device__ __forceinline__ void cp16(uint32_t dst, const void* src) {
    asm volatile("cp.async.cg.shared.global [%0], [%1], 16;"
                 :: "r"(dst), "l"((unsigned long long)__cvta_generic_to_global(src))
                 : "memory");
}
__device__ __forceinline__ void ldsm4(uint32_t* r, uint32_t addr) {
    asm volatile("ldmatrix.sync.aligned.m8n8.x4.shared.b16 {%0,%1,%2,%3}, [%4];"
                 : "=r"(r[0]), "=r"(r[1]), "=r"(r[2]), "=r"(r[3]) : "r"(addr));
}
__device__ __forceinline__ void mma_fp16(float* c, const uint32_t* a,
                                         uint32_t b0, uint32_t b1) {
    asm volatile(
        "mma.sync.aligned.m16n8k16.row.col.f32.f16.f16.f32 "
        "{%0,%1,%2,%3}, {%4,%5,%6,%7}, {%8,%9}, {%0,%1,%2,%3};"
        : "+f"(c[0]), "+f"(c[1]), "+f"(c[2]), "+f"(c[3])
        : "r"(a[0]), "r"(a[1]), "r"(a[2]), "r"(a[3]), "r"(b0), "r"(b1));
}
// packed fp32x2 (Blackwell FFMA2 — PTX-only)
__device__ __forceinline__ unsigned long long dup_f32(float x) {
    unsigned long long r;
    asm("mov.b64 %0, {%1, %1};" : "=l"(r) : "f"(x));
    return r;
}
__device__ __forceinline__ unsigned long long pack_f32(float lo, float hi) {
    unsigned long long r;
    asm("mov.b64 %0, {%1, %2};" : "=l"(r) : "f"(lo), "f"(hi));
    return r;
}
__device__ __forceinline__ void fma2(unsigned long long& d,
                                     unsigned long long a,
                                     unsigned long long b) {
    asm("fma.rn.f32x2 %0, %1, %2, %0;" : "+l"(d) : "l"(a), "l"(b));
}
__device__ __forceinline__ void unpack2(unsigned long long v, float& lo, float& hi) {
    asm("mov.b64 {%0, %1}, %2;" : "=f"(lo), "=f"(hi) : "l"(v));
}
__device__ __forceinline__ void h8_to_f8(uint4 u, float* f) {
    const __half2* hp = (const __half2*)&u;
    float2 f0 = __half22float2(hp[0]);
    float2 f1 = __half22float2(hp[1]);
    float2 f2 = __half22float2(hp[2]);
    float2 f3 = __half22float2(hp[3]);
    f[0] = f0.x; f[1] = f0.y; f[2] = f1.x; f[3] = f1.y;
    f[4] = f2.x; f[5] = f2.y; f[6] = f3.x; f[7] = f3.y;
}

extern __shared__ char dyn_smem[];

// ---------------------------------------------------------------------------
// GEMM (single-term fp16, R15 config): C = A_fp16 @ B^T + bias.
// 128 threads / 4 warps, warp tile 64x64 (MMA:ldsm = 4:1), BM=BN=128, BK=64,
// 3-stage cp.async, 2 CTAs/SM.
// ---------------------------------------------------------------------------
#define BM 128
#define BN 128
#define BK 64
#define NCHUNK (KDIM / BK)    // 12
#define NSTAGE 3
#define A_OFF  0u
#define B_OFF  16384u
#define STG_B  32768u
#define GEMM_SMEM (NSTAGE * STG_B)   // 98304

// 128B rows, slot c16 in [0,8): swizzled by row&7
__device__ __forceinline__ uint32_t swz128(int row, int c16) {
    return (uint32_t)(row * 128 + (((c16) ^ (row & 7)) << 4));
}

__global__ void __launch_bounds__(128, 2)
gemm_mma_kernel(const __half* __restrict__ A,
                const __half* __restrict__ B,
                const float* __restrict__ bias,
                float* __restrict__ C32,
                __half* __restrict__ C16, int N)
{
    const uint32_t sb = (uint32_t)__cvta_generic_to_shared(dyn_smem);
    const int tid    = threadIdx.x;
    const int wid    = tid >> 5;
    const int lane   = tid & 31;
    const int warp_m = wid & 1;     // 64 rows
    const int warp_n = wid >> 1;    // 64 cols
    const int brow   = blockIdx.y * BM;
    const int bcol   = blockIdx.x * BN;

    const char* pA = (const char*)A + (size_t)brow * KPITCH;
    const char* pB = (const char*)B + (size_t)bcol * KPITCH;

    float acc[4][8][4];
#pragma unroll
    for (int mt = 0; mt < 4; mt++)
#pragma unroll
        for (int nt = 0; nt < 8; nt++)
#pragma unroll
            for (int q = 0; q < 4; q++) acc[mt][nt][q] = 0.f;

    auto load_stage = [&](int c, int s) {
        const uint32_t st = sb + s * STG_B;
        const int koff = c * 128;    // 64 halfs = 128 bytes
#pragma unroll
        for (int r = 0; r < 8; r++) {
            int p    = tid + r * 128;      // 0..1023
            int row  = p >> 3;             // 0..127
            int c16  = p & 7;
            uint32_t so = swz128(row, c16);
            size_t   go = (size_t)row * KPITCH + koff + c16 * 16;
            cp16(st + A_OFF + so, pA + go);
            cp16(st + B_OFF + so, pB + go);
        }
        asm volatile("cp.async.commit_group;" ::: "memory");
    };

    load_stage(0, 0);
    load_stage(1, 1);

    for (int c = 0; c < NCHUNK; c++) {
        if (c < NCHUNK - 1)
            asm volatile("cp.async.wait_group 1;" ::: "memory");
        else
            asm volatile("cp.async.wait_group 0;" ::: "memory");
        __syncthreads();

        if (c + 2 < NCHUNK) load_stage(c + 2, (c + 2) % 3);

        const uint32_t st = sb + (c % 3) * STG_B;
#pragma unroll
        for (int ks = 0; ks < 4; ks++) {           // 4 k-steps of 16
            uint32_t a[4][4];
#pragma unroll
            for (int mt = 0; mt < 4; mt++) {
                int row = warp_m * 64 + mt * 16 + (lane & 7) + ((lane >> 3) & 1) * 8;
                int c16 = 2 * ks + ((lane >> 4) & 1);
                ldsm4(a[mt], st + A_OFF + swz128(row, c16));
            }
            uint32_t bh[4][4];
#pragma unroll
            for (int np = 0; np < 4; np++) {
                int rowb = warp_n * 64 + np * 16 + (lane & 7) + ((lane >> 4) & 1) * 8;
                int c16  = 2 * ks + ((lane >> 3) & 1);
                ldsm4(bh[np], st + B_OFF + swz128(rowb, c16));
            }
#pragma unroll
            for (int np = 0; np < 4; np++)
#pragma unroll
                for (int t = 0; t < 2; t++)
#pragma unroll
                    for (int mt = 0; mt < 4; mt++)
                        mma_fp16(acc[mt][np*2+t], a[mt], bh[np][t*2], bh[np][t*2+1]);
        }
    }

    const int row0 = brow + warp_m * 64;
    const int col0 = bcol + warp_n * 64;
#pragma unroll
    for (int mt = 0; mt < 4; mt++) {
#pragma unroll
        for (int nt = 0; nt < 8; nt++) {
            int r  = row0 + mt * 16 + (lane >> 2);
            int cc = col0 + nt * 8 + (lane & 3) * 2;
            float2 bv = *(const float2*)(bias + cc);
            float o0x = acc[mt][nt][0] + bv.x, o0y = acc[mt][nt][1] + bv.y;
            float o1x = acc[mt][nt][2] + bv.x, o1y = acc[mt][nt][3] + bv.y;
            if (C16) {
                __half2 h0 = __floats2half2_rn(o0x, o0y);
                __half2 h1 = __floats2half2_rn(o1x, o1y);
                *(uint32_t*)(C16 + (size_t)r * N + cc)       = *(uint32_t*)&h0;
                *(uint32_t*)(C16 + (size_t)(r + 8) * N + cc) = *(uint32_t*)&h1;
            } else {
                *(float2*)(C32 + (size_t)r * N + cc)       = make_float2(o0x, o0y);
                *(float2*)(C32 + (size_t)(r + 8) * N + cc) = make_float2(o1x, o1y);
            }
        }
    }
}

// ---------------------------------------------------------------------------
// convert f32 -> fp16
// ---------------------------------------------------------------------------
__global__ void __launch_bounds__(256)
conv16_kernel(const float4* __restrict__ in, uint2* __restrict__ out, int n4)
{
    int i = blockIdx.x * 256 + threadIdx.x;
    if (i >= n4) return;
    float4 v = in[i];
    __half2 h0 = __floats2half2_rn(v.x, v.y);
    __half2 h1 = __floats2half2_rn(v.z, v.w);
    uint2 o;
    o.x = *(uint32_t*)&h0;
    o.y = *(uint32_t*)&h1;
    out[i] = o;
}

// ---------------------------------------------------------------------------
// weight transpose to fp16: W[K,N] f32 -> [N,K] fp16
// ---------------------------------------------------------------------------
__global__ void __launch_bounds__(256)
wtrans_kernel(const float* __restrict__ W, __half* __restrict__ hi, int K, int N)
{
    __shared__ float t[32][33];
    const int n0 = blockIdx.x * 32, k0 = blockIdx.y * 32;
    const int tx = threadIdx.x & 31, ty = threadIdx.x >> 5;
#pragma unroll
    for (int r = 0; r < 32; r += 8)
        t[ty + r][tx] = W[(size_t)(k0 + ty + r) * N + n0 + tx];
    __syncthreads();
#pragma unroll
    for (int r = 0; r < 32; r += 8) {
        float v = t[tx][ty + r];
        hi[(size_t)(n0 + ty + r) * K + k0 + tx] = __float2half_rn(v);
    }
}

// ---------------------------------------------------------------------------
// Attention: Round-14 proven design (row-batched, f32x2, fp16 qkv in/out,
// NO q-dedup — its fill had 16-way store conflicts).
// ---------------------------------------------------------------------------
#define VT_STRIDE 52
#define RPW 13

__global__ void __launch_bounds__(128)
attn_kernel(const __half* __restrict__ qkv16,
            const float* __restrict__ mask,
            const float* __restrict__ bias_table,
            __half* __restrict__ out16)
{
    const int bh = blockIdx.x;
    const int b  = bh / NHEADS;
    const int h  = bh - b * NHEADS;
    const int w  = b & (NW - 1);

    __shared__ float qs[NTOK * HDIM];
    __shared__ unsigned long long kp2[HDIM * 32];
    __shared__ float vt[HDIM * VT_STRIDE];
    __shared__ float pbuf[4][RPW][64];
    __shared__ float bt[169];

    const int tid  = threadIdx.x;
    const int warp = tid >> 5, lane = tid & 31;
    const __half* base = qkv16 + (size_t)b * NTOK * QKV_N + h * HDIM;

    for (int idx = tid; idx < NTOK * 4; idx += 128) {
        int i = idx >> 2, m = idx & 3;
        uint4 u = *(const uint4*)(base + (size_t)i * QKV_N + m * 8);
        h8_to_f8(u, &qs[i * HDIM + m * 8]);
    }
    {
        const int d0 = warp * 8;
        const int j  = lane;
        float k1v[8], k2v[8];
        uint4 u1 = *(const uint4*)(base + (size_t)j * QKV_N + DMODEL + d0);
        h8_to_f8(u1, k1v);
        if (j < NTOK - 32) {
            uint4 u2 = *(const uint4*)(base + (size_t)(j + 32) * QKV_N + DMODEL + d0);
            h8_to_f8(u2, k2v);
        } else {
#pragma unroll
            for (int p = 0; p < 8; p++) k2v[p] = 0.f;
        }
#pragma unroll
        for (int p = 0; p < 8; p++)
            kp2[(d0 + p) * 32 + j] = pack_f32(k1v[p], k2v[p]);
    }
    if (tid < NTOK) {
        const __half* vrow = base + (size_t)tid * QKV_N + 2 * DMODEL;
#pragma unroll
        for (int m = 0; m < 4; m++) {
            float f[8];
            h8_to_f8(((const uint4*)vrow)[m], f);
#pragma unroll
            for (int p = 0; p < 8; p++)
                vt[(8 * m + p) * VT_STRIDE + tid] = f[p];
        }
    }
    if (tid >= 64 && tid < 96) {
        int d = tid - 64;
        vt[d * VT_STRIDE + 49] = 0.f;
        vt[d * VT_STRIDE + 50] = 0.f;
        vt[d * VT_STRIDE + 51] = 0.f;
    }
    for (int idx = tid; idx < 169; idx += 128)
        bt[idx] = bias_table[idx * NHEADS + h];
    __syncthreads();

    const float scale = 0.17677669529663687f;
    const float* mrow_base = mask + (size_t)w * NTOK * NTOK;

    const int row0 = warp * RPW;
    const int nr   = (NTOK - row0 < RPW) ? (NTOK - row0) : RPW;

    const int yq  = lane / 7, xq  = lane - yq * 7;
    const int j2l = lane + 32;
    const int yq2 = j2l / 7,  xq2 = j2l - yq2 * 7;

    unsigned long long d12[RPW];
#pragma unroll
    for (int r = 0; r < RPW; r++) d12[r] = 0ull;

#pragma unroll
    for (int m = 0; m < 8; m++) {
        unsigned long long k0 = kp2[(4 * m + 0) * 32 + lane];
        unsigned long long k1 = kp2[(4 * m + 1) * 32 + lane];
        unsigned long long k2 = kp2[(4 * m + 2) * 32 + lane];
        unsigned long long k3 = kp2[(4 * m + 3) * 32 + lane];
#pragma unroll
        for (int r = 0; r < RPW; r++) {
            int i = row0 + ((r < nr) ? r : 0);
            float4 qv = *(const float4*)&qs[i * HDIM + 4 * m];
            fma2(d12[r], k0, dup_f32(qv.x));
            fma2(d12[r], k1, dup_f32(qv.y));
            fma2(d12[r], k2, dup_f32(qv.z));
            fma2(d12[r], k3, dup_f32(qv.w));
        }
    }

#pragma unroll
    for (int r = 0; r < RPW; r++) {
        int i = row0 + ((r < nr) ? r : 0);
        const int yi = i / 7, xi = i - yi * 7;
        const float* mrow = mrow_base + (size_t)i * NTOK;

        float d1, d2;
        unpack2(d12[r], d1, d2);
        float l1 = d1 * scale + bt[(yi - yq + 6) * 13 + (xi - xq + 6)] + mrow[lane];
        float p1 = __expf(l1);
        float p2 = 0.f;
        if (lane < NTOK - 32) {
            float l2 = d2 * scale + bt[(yi - yq2 + 6) * 13 + (xi - xq2 + 6)]
                     + mrow[j2l];
            p2 = __expf(l2);
        }
        float s = p1 + p2;
#pragma unroll
        for (int o = 16; o > 0; o >>= 1)
            s += __shfl_xor_sync(0xffffffffu, s, o);
        float inv = 1.f / s;
        pbuf[warp][r][lane]      = p1 * inv;
        pbuf[warp][r][lane + 32] = p2 * inv;
    }
    __syncwarp();

    unsigned long long a2[RPW];
#pragma unroll
    for (int r = 0; r < RPW; r++) a2[r] = 0ull;

#pragma unroll
    for (int j4 = 0; j4 < 13; j4++) {
        ulonglong2 vq = *(const ulonglong2*)&vt[lane * VT_STRIDE + j4 * 4];
#pragma unroll
        for (int r = 0; r < RPW; r++) {
            ulonglong2 pq = *(const ulonglong2*)&pbuf[warp][r][j4 * 4];
            fma2(a2[r], pq.x, vq.x);
            fma2(a2[r], pq.y, vq.y);
        }
    }

#pragma unroll
    for (int r = 0; r < RPW; r++) {
        if (r < nr) {
            float alo_, ahi_;
            unpack2(a2[r], alo_, ahi_);
            float acc = alo_ + ahi_;
            int i = row0 + r;
            size_t oidx = ((size_t)b * NTOK + i) * DMODEL + h * HDIM + lane;
            out16[oidx] = __float2half_rn(acc);
        }
    }
}

// ---------------------------------------------------------------------------
// launch
// ---------------------------------------------------------------------------
extern "C" void kernel_launch(void* const* d_in, const int* in_sizes, int n_in,
                              void* d_out, int out_size)
{
    const float* x          = (const float*)d_in[0];
    const float* mask       = (const float*)d_in[1];
    const float* qkv_w      = (const float*)d_in[2];
    const float* qkv_b      = (const float*)d_in[3];
    const float* proj_w     = (const float*)d_in[4];
    const float* proj_b     = (const float*)d_in[5];
    const float* bias_table = (const float*)d_in[6];
    float* out = (float*)d_out;

    __half *qkv16, *x16, *a16, *w1hi, *w2hi;
    cudaGetSymbolAddress((void**)&qkv16, g_qkv16);
    cudaGetSymbolAddress((void**)&x16,  g_x16);
    cudaGetSymbolAddress((void**)&a16,  g_a16);
    cudaGetSymbolAddress((void**)&w1hi, g_w1hi);
    cudaGetSymbolAddress((void**)&w2hi, g_w2hi);

    cudaFuncSetAttribute(gemm_mma_kernel,
                         cudaFuncAttributeMaxDynamicSharedMemorySize, GEMM_SMEM);

    // 0) conversions
    {
        int n4 = (MROWS * KDIM) / 4;
        conv16_kernel<<<(n4 + 255) / 256, 256>>>((const float4*)x, (uint2*)x16, n4);
        dim3 g1(QKV_N / 32, KDIM / 32);
        wtrans_kernel<<<g1, 256>>>(qkv_w, w1hi, KDIM, QKV_N);
        dim3 g2(DMODEL / 32, KDIM / 32);
        wtrans_kernel<<<g2, 256>>>(proj_w, w2hi, KDIM, DMODEL);
    }
    // 1) QKV GEMM (single-term fp16, BK=64, 64x64 warp tiles) -> fp16
    {
        dim3 grid(QKV_N / BN, MROWS / BM);
        gemm_mma_kernel<<<grid, 128, GEMM_SMEM>>>(x16, w1hi,
                                                  qkv_b, nullptr, qkv16, QKV_N);
    }
    // 2) attention (R14 row-batched, fp16 in/out)
    attn_kernel<<<B_WIN * NHEADS, 128>>>(qkv16, mask, bias_table, a16);

    // 3) proj GEMM (single-term fp16) -> fp32 d_out
    {
        dim3 grid(DMODEL / BN, MROWS / BM);
        gemm_mma_kernel<<<grid, 128, GEMM_SMEM>>>(a16, w2hi,
                                                  proj_b, out, nullptr, DMODEL);
    }
}

// round 17
// speedup vs baseline: 1.0854x; 1.0041x over previous
#include <cuda_runtime.h>
#include <cuda_fp16.h>
#include <cuda_bf16.h>
#include <cstdint>

// ---------------------------------------------------------------------------
// Problem constants
// ---------------------------------------------------------------------------
#define B_WIN   2048
#define NTOK    49
#define DMODEL  768
#define NHEADS  24
#define HDIM    32
#define NW      64
#define MROWS   (B_WIN * NTOK)     // 100352
#define QKV_N   (3 * DMODEL)       // 2304
#define KDIM    768
#define KPITCH  (KDIM * 2)         // bytes per K-major row (fp16)

// ---------------------------------------------------------------------------
// scratch (__device__ globals, allocation-free)
// ---------------------------------------------------------------------------
__device__ __half g_qkv16[(size_t)MROWS * QKV_N];
__device__ __half g_x16 [(size_t)MROWS * KDIM];
__device__ __half g_a16 [(size_t)MROWS * KDIM];
__device__ __half g_w1hi[(size_t)QKV_N * KDIM];
__device__ __half g_w2hi[(size_t)DMODEL * KDIM];

// ---------------------------------------------------------------------------
// PTX helpers
// ---------------------------------------------------------------------------
__device__ __forceinline__ void cp16(uint32_t dst, const void* src) {
    asm volatile("cp.async.cg.shared.global [%0], [%1], 16;"
                 :: "r"(dst), "l"((unsigned long long)__cvta_generic_to_global(src))
                 : "memory");
}
__device__ __forceinline__ void ldsm4(uint32_t* r, uint32_t addr) {
    asm volatile("ldmatrix.sync.aligned.m8n8.x4.shared.b16 {%0,%1,%2,%3}, [%4];"
                 : "=r"(r[0]), "=r"(r[1]), "=r"(r[2]), "=r"(r[3]) : "r"(addr));
}
__device__ __forceinline__ void mma_fp16(float* c, const uint32_t* a,
                                         uint32_t b0, uint32_t b1) {
    asm volatile(
        "mma.sync.aligned.m16n8k16.row.col.f32.f16.f16.f32 "
        "{%0,%1,%2,%3}, {%4,%5,%6,%7}, {%8,%9}, {%0,%1,%2,%3};"
        : "+f"(c[0]), "+f"(c[1]), "+f"(c[2]), "+f"(c[3])
        : "r"(a[0]), "r"(a[1]), "r"(a[2]), "r"(a[3]), "r"(b0), "r"(b1));
}
// packed fp32x2 (Blackwell FFMA2 — PTX-only)
__device__ __forceinline__ unsigned long long dup_f32(float x) {
    unsigned long long r;
    asm("mov.b64 %0, {%1, %1};" : "=l"(r) : "f"(x));
    return r;
}
__device__ __forceinline__ unsigned long long pack_f32(float lo, float hi) {
    unsigned long long r;
    asm("mov.b64 %0, {%1, %2};" : "=l"(r) : "f"(lo), "f"(hi));
    return r;
}
__device__ __forceinline__ void fma2(unsigned long long& d,
                                     unsigned long long a,
                                     unsigned long long b) {
    asm("fma.rn.f32x2 %0, %1, %2, %0;" : "+l"(d) : "l"(a), "l"(b));
}
__device__ __forceinline__ void unpack2(unsigned long long v, float& lo, float& hi) {
    asm("mov.b64 {%0, %1}, %2;" : "=f"(lo), "=f"(hi) : "l"(v));
}
__device__ __forceinline__ void h8_to_f8(uint4 u, float* f) {
    const __half2* hp = (const __half2*)&u;
    float2 f0 = __half22float2(hp[0]);
    float2 f1 = __half22float2(hp[1]);
    float2 f2 = __half22float2(hp[2]);
    float2 f3 = __half22float2(hp[3]);
    f[0] = f0.x; f[1] = f0.y; f[2] = f1.x; f[3] = f1.y;
    f[4] = f2.x; f[5] = f2.y; f[6] = f3.x; f[7] = f3.y;
}

extern __shared__ char dyn_smem[];

// ---------------------------------------------------------------------------
// GEMM (single-term fp16): C = A_fp16 @ B^T + bias.
// 128 threads / 4 warps, warp tile 64x64, BM=BN=128, BK=64, 3-stage cp.async,
// 2 CTAs/SM. Fragments DOUBLE-BUFFERED: ldsm for k-step ks+1 issued before
// the MMAs of ks, so ldsm latency hides under the tensor stream.
// ---------------------------------------------------------------------------
#define BM 128
#define BN 128
#define BK 64
#define NCHUNK (KDIM / BK)    // 12
#define NSTAGE 3
#define A_OFF  0u
#define B_OFF  16384u
#define STG_B  32768u
#define GEMM_SMEM (NSTAGE * STG_B)   // 98304

// 128B rows, slot c16 in [0,8): swizzled by row&7
__device__ __forceinline__ uint32_t swz128(int row, int c16) {
    return (uint32_t)(row * 128 + (((c16) ^ (row & 7)) << 4));
}

__global__ void __launch_bounds__(128, 2)
gemm_mma_kernel(const __half* __restrict__ A,
                const __half* __restrict__ B,
                const float* __restrict__ bias,
                float* __restrict__ C32,
                __half* __restrict__ C16, int N)
{
    const uint32_t sb = (uint32_t)__cvta_generic_to_shared(dyn_smem);
    const int tid    = threadIdx.x;
    const int wid    = tid >> 5;
    const int lane   = tid & 31;
    const int warp_m = wid & 1;     // 64 rows
    const int warp_n = wid >> 1;    // 64 cols
    const int brow   = blockIdx.y * BM;
    const int bcol   = blockIdx.x * BN;

    const char* pA = (const char*)A + (size_t)brow * KPITCH;
    const char* pB = (const char*)B + (size_t)bcol * KPITCH;

    float acc[4][8][4];
#pragma unroll
    for (int mt = 0; mt < 4; mt++)
#pragma unroll
        for (int nt = 0; nt < 8; nt++)
#pragma unroll
            for (int q = 0; q < 4; q++) acc[mt][nt][q] = 0.f;

    // precomputed per-lane fragment row/col components
    const int arow = warp_m * 64 + (lane & 7) + ((lane >> 3) & 1) * 8;
    const int ac16 = (lane >> 4) & 1;
    const int brow_f = warp_n * 64 + (lane & 7) + ((lane >> 4) & 1) * 8;
    const int bc16 = (lane >> 3) & 1;

    auto load_stage = [&](int c, int s) {
        const uint32_t st = sb + s * STG_B;
        const int koff = c * 128;
#pragma unroll
        for (int r = 0; r < 8; r++) {
            int p    = tid + r * 128;
            int row  = p >> 3;
            int c16  = p & 7;
            uint32_t so = swz128(row, c16);
            size_t   go = (size_t)row * KPITCH + koff + c16 * 16;
            cp16(st + A_OFF + so, pA + go);
            cp16(st + B_OFF + so, pB + go);
        }
        asm volatile("cp.async.commit_group;" ::: "memory");
    };

    load_stage(0, 0);
    load_stage(1, 1);

    uint32_t afr[2][4][4], bfr[2][4][4];

    for (int c = 0; c < NCHUNK; c++) {
        if (c < NCHUNK - 1)
            asm volatile("cp.async.wait_group 1;" ::: "memory");
        else
            asm volatile("cp.async.wait_group 0;" ::: "memory");
        __syncthreads();

        if (c + 2 < NCHUNK) load_stage(c + 2, (c + 2) % 3);

        const uint32_t st = sb + (c % 3) * STG_B;

        // preload fragments for ks=0
#pragma unroll
        for (int mt = 0; mt < 4; mt++)
            ldsm4(afr[0][mt], st + A_OFF + swz128(arow + mt * 16, ac16));
#pragma unroll
        for (int np = 0; np < 4; np++)
            ldsm4(bfr[0][np], st + B_OFF + swz128(brow_f + np * 16, bc16));

#pragma unroll
        for (int ks = 0; ks < 4; ks++) {
            const int cur = ks & 1;
            if (ks < 3) {
                const int nxt = cur ^ 1;
                const int c16a = 2 * (ks + 1) + ac16;
                const int c16b = 2 * (ks + 1) + bc16;
#pragma unroll
                for (int mt = 0; mt < 4; mt++)
                    ldsm4(afr[nxt][mt], st + A_OFF + swz128(arow + mt * 16, c16a));
#pragma unroll
                for (int np = 0; np < 4; np++)
                    ldsm4(bfr[nxt][np], st + B_OFF + swz128(brow_f + np * 16, c16b));
            }
#pragma unroll
            for (int np = 0; np < 4; np++)
#pragma unroll
                for (int t = 0; t < 2; t++)
#pragma unroll
                    for (int mt = 0; mt < 4; mt++)
                        mma_fp16(acc[mt][np*2+t], afr[cur][mt],
                                 bfr[cur][np][t*2], bfr[cur][np][t*2+1]);
        }
    }

    const int row0 = brow + warp_m * 64;
    const int col0 = bcol + warp_n * 64;
#pragma unroll
    for (int mt = 0; mt < 4; mt++) {
#pragma unroll
        for (int nt = 0; nt < 8; nt++) {
            int r  = row0 + mt * 16 + (lane >> 2);
            int cc = col0 + nt * 8 + (lane & 3) * 2;
            float2 bv = *(const float2*)(bias + cc);
            float o0x = acc[mt][nt][0] + bv.x, o0y = acc[mt][nt][1] + bv.y;
            float o1x = acc[mt][nt][2] + bv.x, o1y = acc[mt][nt][3] + bv.y;
            if (C16) {
                __half2 h0 = __floats2half2_rn(o0x, o0y);
                __half2 h1 = __floats2half2_rn(o1x, o1y);
                *(uint32_t*)(C16 + (size_t)r * N + cc)       = *(uint32_t*)&h0;
                *(uint32_t*)(C16 + (size_t)(r + 8) * N + cc) = *(uint32_t*)&h1;
            } else {
                *(float2*)(C32 + (size_t)r * N + cc)       = make_float2(o0x, o0y);
                *(float2*)(C32 + (size_t)(r + 8) * N + cc) = make_float2(o1x, o1y);
            }
        }
    }
}

// ---------------------------------------------------------------------------
// convert f32 -> fp16
// ---------------------------------------------------------------------------
__global__ void __launch_bounds__(256)
conv16_kernel(const float4* __restrict__ in, uint2* __restrict__ out, int n4)
{
    int i = blockIdx.x * 256 + threadIdx.x;
    if (i >= n4) return;
    float4 v = in[i];
    __half2 h0 = __floats2half2_rn(v.x, v.y);
    __half2 h1 = __floats2half2_rn(v.z, v.w);
    uint2 o;
    o.x = *(uint32_t*)&h0;
    o.y = *(uint32_t*)&h1;
    out[i] = o;
}

// ---------------------------------------------------------------------------
// weight transpose to fp16: W[K,N] f32 -> [N,K] fp16
// ---------------------------------------------------------------------------
__global__ void __launch_bounds__(256)
wtrans_kernel(const float* __restrict__ W, __half* __restrict__ hi, int K, int N)
{
    __shared__ float t[32][33];
    const int n0 = blockIdx.x * 32, k0 = blockIdx.y * 32;
    const int tx = threadIdx.x & 31, ty = threadIdx.x >> 5;
#pragma unroll
    for (int r = 0; r < 32; r += 8)
        t[ty + r][tx] = W[(size_t)(k0 + ty + r) * N + n0 + tx];
    __syncthreads();
#pragma unroll
    for (int r = 0; r < 32; r += 8) {
        float v = t[tx][ty + r];
        hi[(size_t)(n0 + ty + r) * K + k0 + tx] = __float2half_rn(v);
    }
}

// ---------------------------------------------------------------------------
// Attention: Round-14/16 proven design (row-batched, f32x2, fp16 in/out).
// ---------------------------------------------------------------------------
#define VT_STRIDE 52
#define RPW 13

__global__ void __launch_bounds__(128)
attn_kernel(const __half* __restrict__ qkv16,
            const float* __restrict__ mask,
            const float* __restrict__ bias_table,
            __half* __restrict__ out16)
{
    const int bh = blockIdx.x;
    const int b  = bh / NHEADS;
    const int h  = bh - b * NHEADS;
    const int w  = b & (NW - 1);

    __shared__ float qs[NTOK * HDIM];
    __shared__ unsigned long long kp2[HDIM * 32];
    __shared__ float vt[HDIM * VT_STRIDE];
    __shared__ float pbuf[4][RPW][64];
    __shared__ float bt[169];

    const int tid  = threadIdx.x;
    const int warp = tid >> 5, lane = tid & 31;
    const __half* base = qkv16 + (size_t)b * NTOK * QKV_N + h * HDIM;

    for (int idx = tid; idx < NTOK * 4; idx += 128) {
        int i = idx >> 2, m = idx & 3;
        uint4 u = *(const uint4*)(base + (size_t)i * QKV_N + m * 8);
        h8_to_f8(u, &qs[i * HDIM + m * 8]);
    }
    {
        const int d0 = warp * 8;
        const int j  = lane;
        float k1v[8], k2v[8];
        uint4 u1 = *(const uint4*)(base + (size_t)j * QKV_N + DMODEL + d0);
        h8_to_f8(u1, k1v);
        if (j < NTOK - 32) {
            uint4 u2 = *(const uint4*)(base + (size_t)(j + 32) * QKV_N + DMODEL + d0);
            h8_to_f8(u2, k2v);
        } else {
#pragma unroll
            for (int p = 0; p < 8; p++) k2v[p] = 0.f;
        }
#pragma unroll
        for (int p = 0; p < 8; p++)
            kp2[(d0 + p) * 32 + j] = pack_f32(k1v[p], k2v[p]);
    }
    if (tid < NTOK) {
        const __half* vrow = base + (size_t)tid * QKV_N + 2 * DMODEL;
#pragma unroll
        for (int m = 0; m < 4; m++) {
            float f[8];
            h8_to_f8(((const uint4*)vrow)[m], f);
#pragma unroll
            for (int p = 0; p < 8; p++)
                vt[(8 * m + p) * VT_STRIDE + tid] = f[p];
        }
    }
    if (tid >= 64 && tid < 96) {
        int d = tid - 64;
        vt[d * VT_STRIDE + 49] = 0.f;
        vt[d * VT_STRIDE + 50] = 0.f;
        vt[d * VT_STRIDE + 51] = 0.f;
    }
    for (int idx = tid; idx < 169; idx += 128)
        bt[idx] = bias_table[idx * NHEADS + h];
    __syncthreads();

    const float scale = 0.17677669529663687f;
    const float* mrow_base = mask + (size_t)w * NTOK * NTOK;

    const int row0 = warp * RPW;
    const int nr   = (NTOK - row0 < RPW) ? (NTOK - row0) : RPW;

    const int yq  = lane / 7, xq  = lane - yq * 7;
    const int j2l = lane + 32;
    const int yq2 = j2l / 7,  xq2 = j2l - yq2 * 7;

    unsigned long long d12[RPW];
#pragma unroll
    for (int r = 0; r < RPW; r++) d12[r] = 0ull;

#pragma unroll
    for (int m = 0; m < 8; m++) {
        unsigned long long k0 = kp2[(4 * m + 0) * 32 + lane];
        unsigned long long k1 = kp2[(4 * m + 1) * 32 + lane];
        unsigned long long k2 = kp2[(4 * m + 2) * 32 + lane];
        unsigned long long k3 = kp2[(4 * m + 3) * 32 + lane];
#pragma unroll
        for (int r = 0; r < RPW; r++) {
            int i = row0 + ((r < nr) ? r : 0);
            float4 qv = *(const float4*)&qs[i * HDIM + 4 * m];
            fma2(d12[r], k0, dup_f32(qv.x));
            fma2(d12[r], k1, dup_f32(qv.y));
            fma2(d12[r], k2, dup_f32(qv.z));
            fma2(d12[r], k3, dup_f32(qv.w));
        }
    }

#pragma unroll
    for (int r = 0; r < RPW; r++) {
        int i = row0 + ((r < nr) ? r : 0);
        const int yi = i / 7, xi = i - yi * 7;
        const float* mrow = mrow_base + (size_t)i * NTOK;

        float d1, d2;
        unpack2(d12[r], d1, d2);
        float l1 = d1 * scale + bt[(yi - yq + 6) * 13 + (xi - xq + 6)] + mrow[lane];
        float p1 = __expf(l1);
        float p2 = 0.f;
        if (lane < NTOK - 32) {
            float l2 = d2 * scale + bt[(yi - yq2 + 6) * 13 + (xi - xq2 + 6)]
                     + mrow[j2l];
            p2 = __expf(l2);
        }
        float s = p1 + p2;
#pragma unroll
        for (int o = 16; o > 0; o >>= 1)
            s += __shfl_xor_sync(0xffffffffu, s, o);
        float inv = 1.f / s;
        pbuf[warp][r][lane]      = p1 * inv;
        pbuf[warp][r][lane + 32] = p2 * inv;
    }
    __syncwarp();

    unsigned long long a2[RPW];
#pragma unroll
    for (int r = 0; r < RPW; r++) a2[r] = 0ull;

#pragma unroll
    for (int j4 = 0; j4 < 13; j4++) {
        ulonglong2 vq = *(const ulonglong2*)&vt[lane * VT_STRIDE + j4 * 4];
#pragma unroll
        for (int r = 0; r < RPW; r++) {
            ulonglong2 pq = *(const ulonglong2*)&pbuf[warp][r][j4 * 4];
            fma2(a2[r], pq.x, vq.x);
            fma2(a2[r], pq.y, vq.y);
        }
    }

#pragma unroll
    for (int r = 0; r < RPW; r++) {
        if (r < nr) {
            float alo_, ahi_;
            unpack2(a2[r], alo_, ahi_);
            float acc = alo_ + ahi_;
            int i = row0 + r;
            size_t oidx = ((size_t)b * NTOK + i) * DMODEL + h * HDIM + lane;
            out16[oidx] = __float2half_rn(acc);
        }
    }
}

// ---------------------------------------------------------------------------
// launch
// ---------------------------------------------------------------------------
extern "C" void kernel_launch(void* const* d_in, const int* in_sizes, int n_in,
                              void* d_out, int out_size)
{
    const float* x          = (const float*)d_in[0];
    const float* mask       = (const float*)d_in[1];
    const float* qkv_w      = (const float*)d_in[2];
    const float* qkv_b      = (const float*)d_in[3];
    const float* proj_w     = (const float*)d_in[4];
    const float* proj_b     = (const float*)d_in[5];
    const float* bias_table = (const float*)d_in[6];
    float* out = (float*)d_out;

    __half *qkv16, *x16, *a16, *w1hi, *w2hi;
    cudaGetSymbolAddress((void**)&qkv16, g_qkv16);
    cudaGetSymbolAddress((void**)&x16,  g_x16);
    cudaGetSymbolAddress((void**)&a16,  g_a16);
    cudaGetSymbolAddress((void**)&w1hi, g_w1hi);
    cudaGetSymbolAddress((void**)&w2hi, g_w2hi);

    cudaFuncSetAttribute(gemm_mma_kernel,
                         cudaFuncAttributeMaxDynamicSharedMemorySize, GEMM_SMEM);

    // 0) conversions
    {
        int n4 = (MROWS * KDIM) / 4;
        conv16_kernel<<<(n4 + 255) / 256, 256>>>((const float4*)x, (uint2*)x16, n4);
        dim3 g1(QKV_N / 32, KDIM / 32);
        wtrans_kernel<<<g1, 256>>>(qkv_w, w1hi, KDIM, QKV_N);
        dim3 g2(DMODEL / 32, KDIM / 32);
        wtrans_kernel<<<g2, 256>>>(proj_w, w2hi, KDIM, DMODEL);
    }
    // 1) QKV GEMM (single-term fp16, double-buffered fragments) -> fp16
    {
        dim3 grid(QKV_N / BN, MROWS / BM);
        gemm_mma_kernel<<<grid, 128, GEMM_SMEM>>>(x16, w1hi,
                                                  qkv_b, nullptr, qkv16, QKV_N);
    }
    // 2) attention (row-batched, fp16 in/out)
    attn_kernel<<<B_WIN * NHEADS, 128>>>(qkv16, mask, bias_table, a16);

    // 3) proj GEMM (single-term fp16) -> fp32 d_out
    {
        dim3 grid(DMODEL / BN, MROWS / BM);
        gemm_mma_kernel<<<grid, 128, GEMM_SMEM>>>(a16, w2hi,
                                                  proj_b, out, nullptr, DMODEL);
    }
}